// round 15
// baseline (speedup 1.0000x reference)
#include <cuda_runtime.h>
#include <cuda_fp16.h>
#include <cstdint>
#include <math.h>

#define HIDDEN      2048
#define GATE_IN     2608
#define GATE_IN_PAD 2624        // 41 * 64
#define STAT_W      576         // 560 data + 16 zero pad (halves)
#define GATE_HID    1024
#define NH          16
#define HD          128
#define NP          5
#define OUT_DIM     80
#define MAX_NT      8192

// GEMM1: CTA 128x256, 8 warps (2M x 4N, warp 64x64), fp16 m16n8k16 + ldmatrix
#define KCH         64
#define NCHUNK      (GATE_IN_PAD / KCH)        // 41
#define STRH        72
#define G1_A_H      (128 * STRH)
#define G1_B_H      (256 * STRH)
#define G1_STAGE_B  ((G1_A_H + G1_B_H) * 2)    // 55296 B
#define GEMM1_SMEM  (3 * G1_STAGE_B)           // 165888 B

// EPI (gemm2+softmax+output): CTA 64(M) x 80(N), 8 warps (4M x 2N)
#define G2_NCH      (GATE_HID / KCH)           // 16
#define G2_A_H      (64 * STRH)
#define G2_B_H      (80 * STRH)
#define EPI_SMEM    (2 * (G2_A_H + G2_B_H) * 2)   // 41472 B

// fused prep grid layout (1 token per stats CTA)
#define NB_STATS    MAX_NT                     // 8192
#define NB_W1       656
#define NB_W2       20
#define NB_TOTAL    (NB_STATS + NB_W1 + NB_W2 + 1)

#define N_MBLK      (MAX_NT / 128)             // 64 gemm1 M-blocks

// Static scratch
__device__ __half g_hid_h[(size_t)MAX_NT * HIDDEN];
__device__ __half g_stats[(size_t)MAX_NT * STAT_W];
__device__ __half g_w1p[(size_t)GATE_HID * GATE_IN_PAD];
__device__ __half g_w2p[(size_t)OUT_DIM * GATE_HID];
__device__ __half g_h[(size_t)MAX_NT * GATE_HID];
__device__ int    g_done[N_MBLK];

// ---------------------------------------------------------------------------
// helpers
// ---------------------------------------------------------------------------
__device__ __forceinline__ float wredsum(float v) {
#pragma unroll
    for (int o = 16; o; o >>= 1) v += __shfl_xor_sync(0xffffffffu, v, o);
    return v;
}
__device__ __forceinline__ void cp_async16(uint32_t dst, const void* src) {
    asm volatile("cp.async.cg.shared.global [%0], [%1], 16;" :: "r"(dst), "l"(src));
}
__device__ __forceinline__ uint32_t smem_u32(const void* p) {
    uint32_t a;
    asm("{ .reg .u64 t; cvta.to.shared.u64 t, %1; cvt.u32.u64 %0, t; }" : "=r"(a) : "l"(p));
    return a;
}
__device__ __forceinline__ float gelu(float x) {
    return 0.5f * x * (1.0f + erff(x * 0.70710678118654752f));
}
__device__ __forceinline__ void ldmatrix_x4(uint32_t r[4], uint32_t addr) {
    asm volatile("ldmatrix.sync.aligned.m8n8.x4.shared.b16 {%0,%1,%2,%3}, [%4];"
                 : "=r"(r[0]), "=r"(r[1]), "=r"(r[2]), "=r"(r[3]) : "r"(addr));
}
#define GDC_TRIGGER() asm volatile("griddepcontrol.launch_dependents;" ::: "memory")
#define GDC_WAIT()    asm volatile("griddepcontrol.wait;" ::: "memory")
__device__ __forceinline__ void mma_f16_16x8x16(float c[4],
                                                uint32_t a0, uint32_t a1,
                                                uint32_t a2, uint32_t a3,
                                                uint32_t b0, uint32_t b1) {
    asm("mma.sync.aligned.m16n8k16.row.col.f32.f16.f16.f32 "
        "{%0,%1,%2,%3}, {%4,%5,%6,%7}, {%8,%9}, {%0,%1,%2,%3};"
        : "+f"(c[0]), "+f"(c[1]), "+f"(c[2]), "+f"(c[3])
        : "r"(a0), "r"(a1), "r"(a2), "r"(a3), "r"(b0), "r"(b1));
}
__device__ __forceinline__ uint2 f4_to_h4(float4 v) {
    __half2 h0 = __floats2half2_rn(v.x, v.y);
    __half2 h1 = __floats2half2_rn(v.z, v.w);
    uint2 u;
    u.x = *reinterpret_cast<uint32_t*>(&h0);
    u.y = *reinterpret_cast<uint32_t*>(&h1);
    return u;
}

// ---------------------------------------------------------------------------
// Fused prep+stats kernel (R12 shape) + g_done reset.
// ---------------------------------------------------------------------------
__global__ void __launch_bounds__(512) fused_prep_kernel(
    const float* __restrict__ hidden,
    const float* __restrict__ p0, const float* __restrict__ p1,
    const float* __restrict__ p2, const float* __restrict__ p3,
    const float* __restrict__ p4,
    const float* __restrict__ W1, const float* __restrict__ W2,
    float* __restrict__ out, int tail_start, int out_total)
{
    const int bid = blockIdx.x, tid = threadIdx.x;

    if (bid >= NB_STATS) {
        const int pb = bid - NB_STATS;
        if (pb < NB_W1) {
#pragma unroll
            for (int j = 0; j < 2; j++) {
                const int idx = pb * 1024 + tid + j * 512;
                const int row = idx / (GATE_IN_PAD / 4);
                const int c4  = idx % (GATE_IN_PAD / 4);
                float4 v = {0.f, 0.f, 0.f, 0.f};
                if (c4 < GATE_IN / 4)
                    v = reinterpret_cast<const float4*>(W1 + (size_t)row * GATE_IN)[c4];
                reinterpret_cast<uint2*>(g_w1p + (size_t)row * GATE_IN_PAD)[c4] = f4_to_h4(v);
            }
        } else if (pb < NB_W1 + NB_W2) {
#pragma unroll
            for (int j = 0; j < 2; j++) {
                const int idx = (pb - NB_W1) * 1024 + tid + j * 512;
                float4 v = reinterpret_cast<const float4*>(W2)[idx];
                reinterpret_cast<uint2*>(g_w2p)[idx] = f4_to_h4(v);
            }
        } else {
            if (tid < N_MBLK) g_done[tid] = 0;              // reset per replay
            for (int i = tail_start + tid; i < out_total; i += 512) out[i] = 0.0f;
        }
        return;
    }

    const int t = bid;
    __half* gate = g_stats + (size_t)t * STAT_W;

    {
        const float4 hv = (reinterpret_cast<const float4*>(hidden) + (size_t)t * (HIDDEN / 4))[tid];
        reinterpret_cast<uint2*>(g_hid_h + (size_t)t * HIDDEN)[tid] = f4_to_h4(hv);
    }
    if (tid < 4) {
        uint2 z = {0u, 0u};
        reinterpret_cast<uint2*>(gate + 560)[tid] = z;
    }

    const int w = tid >> 5, lane = tid & 31;
    const float* pp[NP] = {p0, p1, p2, p3, p4};
    const size_t base = (size_t)t * (NH * HD) + (size_t)w * HD + lane * 4;

    float4 v[NP];
#pragma unroll
    for (int p = 0; p < NP; p++) v[p] = *reinterpret_cast<const float4*>(pp[p] + base);

    float vals[25];
#pragma unroll
    for (int p = 0; p < NP; p++) {
        vals[p]      = v[p].x + v[p].y + v[p].z + v[p].w;
        vals[5 + p]  = v[p].x * v[p].x + v[p].y * v[p].y + v[p].z * v[p].z + v[p].w * v[p].w;
        vals[10 + p] = fabsf(v[p].x) + fabsf(v[p].y) + fabsf(v[p].z) + fabsf(v[p].w);
    }
    {
        int k = 15;
#pragma unroll
        for (int p = 0; p < NP; p++)
#pragma unroll
            for (int q = p + 1; q < NP; q++)
                vals[k++] = v[p].x * v[q].x + v[p].y * v[q].y + v[p].z * v[q].z + v[p].w * v[q].w;
    }
#pragma unroll
    for (int i = 0; i < 25; i++) vals[i] = wredsum(vals[i]);

    if (lane == 0) {
        const float inv = 1.0f / 128.0f;
        float sq[NP];
#pragma unroll
        for (int p = 0; p < NP; p++) {
            float mean = vals[p] * inv;
            sq[p] = vals[5 + p];
            float l2 = sqrtf(sq[p]);
            float var = sq[p] * inv - mean * mean;
            float am  = vals[10 + p] * inv;
            __half* s = gate + w * (NP * 4) + p * 4;
            s[0] = __float2half_rn(mean); s[1] = __float2half_rn(var);
            s[2] = __float2half_rn(am);   s[3] = __float2half_rn(l2);
            gate[320 + w * NP + p] = __float2half_rn(l2);
        }
        int kk = 0;
#pragma unroll
        for (int p = 0; p < NP; p++)
#pragma unroll
            for (int q = p + 1; q < NP; q++) {
                float d2 = sq[p] + sq[q] - 2.0f * vals[15 + kk];
                gate[400 + w * 10 + kk] = __float2half_rn(sqrtf(fmaxf(d2, 0.0f)));
                kk++;
            }
    }
}

// ---------------------------------------------------------------------------
// GEMM1 fp16 mma + ldmatrix. 224-reg cap so one epi CTA co-resides per SM.
// Publishes per-M-block completion counters.
// ---------------------------------------------------------------------------
__device__ __forceinline__ void g1_load(uint32_t stage_s,
                                        const __half* __restrict__ hid,
                                        const __half* __restrict__ st,
                                        const __half* __restrict__ Bm,
                                        int k0, int tid)
{
    const uint32_t a_s = stage_s;
    const uint32_t b_s = stage_s + G1_A_H * 2;
    const __half* asrc;
    int astride, ak;
    if (k0 < HIDDEN) { asrc = hid; astride = HIDDEN; ak = k0; }
    else             { asrc = st;  astride = STAT_W; ak = k0 - HIDDEN; }
#pragma unroll
    for (int j = 0; j < 4; j++) {
        const int idx = tid + j * 256;
        const int m  = idx >> 3;
        const int ks = (idx & 7) << 3;
        cp_async16(a_s + (uint32_t)(m * STRH + ks) * 2,
                   asrc + (size_t)m * astride + ak + ks);
    }
#pragma unroll
    for (int j = 0; j < 8; j++) {
        const int idx = tid + j * 256;
        const int m  = idx >> 3;
        const int ks = (idx & 7) << 3;
        cp_async16(b_s + (uint32_t)(m * STRH + ks) * 2,
                   Bm + (size_t)m * GATE_IN_PAD + k0 + ks);
    }
}

__global__ void __launch_bounds__(288, 1) gemm1_mma_kernel(const float* __restrict__ b1)
{
    GDC_WAIT();      // prep complete
    GDC_TRIGGER();   // allow epi to launch (fires once ALL gemm1 CTAs start)

    extern __shared__ __half smem[];
    const uint32_t s0 = smem_u32(smem);

    const int tid  = threadIdx.x;
    const int wid  = tid >> 5, lane = tid & 31;
    const int wm   = (wid & 1) * 64;
    const int wn   = (wid >> 1) * 64;
    const int g    = lane >> 2;
    const int t2   = (lane & 3) * 2;
    const int quad = lane >> 3;

    const uint32_t a_loff = (uint32_t)(((quad & 1) * 8 + (lane & 7)) * STRH + (quad >> 1) * 8);
    const uint32_t b_loff = (uint32_t)(((quad >> 1) * 8 + (lane & 7)) * STRH + (quad & 1) * 8);

    const __half* hid = g_hid_h + (size_t)blockIdx.y * 128 * HIDDEN;
    const __half* st  = g_stats + (size_t)blockIdx.y * 128 * STAT_W;
    const __half* Bm  = g_w1p   + (size_t)blockIdx.x * 256 * GATE_IN_PAD;

    float acc[4][8][4];
#pragma unroll
    for (int i = 0; i < 4; i++)
#pragma unroll
        for (int j = 0; j < 8; j++)
#pragma unroll
            for (int r = 0; r < 4; r++) acc[i][j][r] = 0.0f;

    g1_load(s0, hid, st, Bm, 0, tid);
    asm volatile("cp.async.commit_group;" ::: "memory");
    g1_load(s0 + G1_STAGE_B, hid, st, Bm, KCH, tid);
    asm volatile("cp.async.commit_group;" ::: "memory");

    int stage_rd = 0;
    for (int i = 0; i < NCHUNK; i++) {
        if (i + 2 < NCHUNK) {
            const int ws = (i + 2) % 3;
            g1_load(s0 + (uint32_t)ws * G1_STAGE_B, hid, st, Bm, (i + 2) * KCH, tid);
        }
        asm volatile("cp.async.commit_group;" ::: "memory");
        asm volatile("cp.async.wait_group 2;" ::: "memory");
        __syncthreads();

        const uint32_t as_u = s0 + (uint32_t)stage_rd * G1_STAGE_B;
        const uint32_t bs_u = as_u + G1_A_H * 2;

#pragma unroll
        for (int kk = 0; kk < KCH; kk += 16) {
            uint32_t a[4][4];
#pragma unroll
            for (int mi = 0; mi < 4; mi++)
                ldmatrix_x4(a[mi],
                            as_u + ((uint32_t)((wm + mi * 16) * STRH + kk) + a_loff) * 2);
            uint32_t b[4][4];
#pragma unroll
            for (int njp = 0; njp < 4; njp++)
                ldmatrix_x4(b[njp],
                            bs_u + ((uint32_t)((wn + njp * 16) * STRH + kk) + b_loff) * 2);
#pragma unroll
            for (int mi = 0; mi < 4; mi++)
#pragma unroll
                for (int njp = 0; njp < 4; njp++) {
                    mma_f16_16x8x16(acc[mi][njp * 2],     a[mi][0], a[mi][1], a[mi][2], a[mi][3],
                                    b[njp][0], b[njp][1]);
                    mma_f16_16x8x16(acc[mi][njp * 2 + 1], a[mi][0], a[mi][1], a[mi][2], a[mi][3],
                                    b[njp][2], b[njp][3]);
                }
        }
        __syncthreads();
        stage_rd = stage_rd + 1 == 3 ? 0 : stage_rd + 1;
    }

    const size_t row_base = (size_t)blockIdx.y * 128 + wm + g;
    const int    col_base = blockIdx.x * 256 + wn + t2;
#pragma unroll
    for (int nj = 0; nj < 8; nj++) {
        const int gc = col_base + nj * 8;
        const float2 bb = *reinterpret_cast<const float2*>(b1 + gc);
#pragma unroll
        for (int mi = 0; mi < 4; mi++) {
            const size_t r0 = row_base + mi * 16;
            __half2 o0 = __floats2half2_rn(gelu(acc[mi][nj][0] + bb.x),
                                           gelu(acc[mi][nj][1] + bb.y));
            __half2 o1 = __floats2half2_rn(gelu(acc[mi][nj][2] + bb.x),
                                           gelu(acc[mi][nj][3] + bb.y));
            *reinterpret_cast<__half2*>(g_h + r0 * GATE_HID + gc)       = o0;
            *reinterpret_cast<__half2*>(g_h + (r0 + 8) * GATE_HID + gc) = o1;
        }
    }

    // publish: this M-block's column-tile is done
    __threadfence();
    __syncthreads();
    if (tid == 0) atomicAdd(&g_done[blockIdx.y], 1);
}

// ---------------------------------------------------------------------------
// EPI: per 64-token block — spin on gemm1 M-block, gemm2 + softmax (smem),
// then weighted path combine for those tokens. 128 CTAs, <=32 regs target
// so it co-resides with gemm1 (224*256 + 32*256 = 65536).
// ---------------------------------------------------------------------------
__global__ void __launch_bounds__(1024, 2) epi_kernel(
    const float* __restrict__ b2, const float* __restrict__ log_temp,
    const float* __restrict__ p0, const float* __restrict__ p1,
    const float* __restrict__ p2, const float* __restrict__ p3,
    const float* __restrict__ p4, float* __restrict__ out)
{
    extern __shared__ __half smem[];
    const uint32_t s0 = smem_u32(smem);

    const int tid  = threadIdx.x;
    const int wid  = tid >> 5, lane = tid & 31;
    const int mw   = wid >> 1;
    const int nw   = wid & 1;
    const int g    = lane >> 2;
    const int t2   = (lane & 3) * 2;

    const int tbase = blockIdx.x * 64;
    const int mblk  = blockIdx.x >> 1;          // gemm1 M-block (128 tokens)

    // spin until all 4 column tiles of this M-block are published
    if (tid == 0) {
        int v;
        do {
            asm volatile("ld.global.acquire.gpu.b32 %0, [%1];" : "=r"(v) : "l"(g_done + mblk));
            if (v < 4) __nanosleep(256);
        } while (v < 4);
    }
    __syncthreads();
    asm volatile("fence.acq_rel.gpu;" ::: "memory");

    const __half* A = g_h + (size_t)tbase * GATE_HID;

    float acc[5][4];
#pragma unroll
    for (int j = 0; j < 5; j++)
#pragma unroll
        for (int r = 0; r < 4; r++) acc[j][r] = 0.0f;

    const uint32_t aoff[2] = {0u, (uint32_t)G2_A_H * 2};
    const uint32_t boff[2] = {(uint32_t)(2 * G2_A_H) * 2,
                              (uint32_t)(2 * G2_A_H + G2_B_H) * 2};

    {
#pragma unroll
        for (int j = 0; j < 2; j++) {
            const int idx = tid + j * 256;
            const int m = idx >> 3, ks = (idx & 7) << 3;
            cp_async16(s0 + aoff[0] + (uint32_t)(m * STRH + ks) * 2,
                       A + (size_t)m * GATE_HID + ks);
        }
#pragma unroll
        for (int j = 0; j < 3; j++) {
            const int idx = tid + j * 256;
            if (idx < 640) {
                const int m = idx >> 3, ks = (idx & 7) << 3;
                cp_async16(s0 + boff[0] + (uint32_t)(m * STRH + ks) * 2,
                           g_w2p + (size_t)m * GATE_HID + ks);
            }
        }
        asm volatile("cp.async.commit_group;" ::: "memory");
    }

    for (int i = 0; i < G2_NCH; i++) {
        const int s = i & 1;
        if (i + 1 < G2_NCH) {
            const int ns = (i + 1) & 1;
            const int k0 = (i + 1) * KCH;
#pragma unroll
            for (int j = 0; j < 2; j++) {
                const int idx = tid + j * 256;
                const int m = idx >> 3, ks = (idx & 7) << 3;
                cp_async16(s0 + aoff[ns] + (uint32_t)(m * STRH + ks) * 2,
                           A + (size_t)m * GATE_HID + k0 + ks);
            }
#pragma unroll
            for (int j = 0; j < 3; j++) {
                const int idx = tid + j * 256;
                if (idx < 640) {
                    const int m = idx >> 3, ks = (idx & 7) << 3;
                    cp_async16(s0 + boff[ns] + (uint32_t)(m * STRH + ks) * 2,
                               g_w2p + (size_t)m * GATE_HID + k0 + ks);
                }
            }
        }
        asm volatile("cp.async.commit_group;" ::: "memory");
        if (i + 1 < G2_NCH) asm volatile("cp.async.wait_group 1;" ::: "memory");
        else                asm volatile("cp.async.wait_group 0;" ::: "memory");
        __syncthreads();

        const __half* as = smem + (s ? G2_A_H : 0);
        const __half* bs = smem + 2 * G2_A_H + (s ? G2_B_H : 0);

#pragma unroll
        for (int kk = 0; kk < KCH; kk += 16) {
            const __half* r0 = as + (mw * 16 + g) * STRH + kk + t2;
            const __half* r1 = as + (mw * 16 + g + 8) * STRH + kk + t2;
            uint32_t a0 = *reinterpret_cast<const uint32_t*>(r0);
            uint32_t a1 = *reinterpret_cast<const uint32_t*>(r1);
            uint32_t a2 = *reinterpret_cast<const uint32_t*>(r0 + 8);
            uint32_t a3 = *reinterpret_cast<const uint32_t*>(r1 + 8);
#pragma unroll
            for (int nj = 0; nj < 5; nj++) {
                const __half* br = bs + (nw * 40 + nj * 8 + g) * STRH + kk + t2;
                mma_f16_16x8x16(acc[nj], a0, a1, a2, a3,
                                *reinterpret_cast<const uint32_t*>(br),
                                *reinterpret_cast<const uint32_t*>(br + 8));
            }
        }
        __syncthreads();
    }

    // logits -> smem, then softmax in place (lg becomes probs)
    float* lg = reinterpret_cast<float*>(smem);
    {
        const int r0 = mw * 16 + g;
        const int c0 = nw * 40 + t2;
#pragma unroll
        for (int nj = 0; nj < 5; nj++) {
            const int c = c0 + nj * 8;
            lg[r0 * OUT_DIM + c]            = acc[nj][0];
            lg[r0 * OUT_DIM + c + 1]        = acc[nj][1];
            lg[(r0 + 8) * OUT_DIM + c]      = acc[nj][2];
            lg[(r0 + 8) * OUT_DIM + c + 1]  = acc[nj][3];
        }
    }
    __syncthreads();

#pragma unroll
    for (int it = 0; it < 4; it++) {
        const int idx = tid + it * 256;
        const int tt = idx >> 4, h = idx & 15;
        const float invt = expf(-log_temp[h]);
        float l[NP], mx = -1e30f;
#pragma unroll
        for (int p = 0; p < NP; p++) {
            l[p] = (lg[tt * OUT_DIM + h * NP + p] + __ldg(b2 + h * NP + p)) * invt;
            mx = fmaxf(mx, l[p]);
        }
        float e[NP], se = 0.f;
#pragma unroll
        for (int p = 0; p < NP; p++) { e[p] = expf(l[p] - mx); se += e[p]; }
        const float ise = 1.0f / se;
        float pr[NP], s2s = 0.f;
#pragma unroll
        for (int p = 0; p < NP; p++) { pr[p] = fmaxf(e[p] * ise, 0.02f); s2s += pr[p]; }
        const float is2 = 1.0f / s2s;
#pragma unroll
        for (int p = 0; p < NP; p++) lg[tt * OUT_DIM + h * NP + p] = pr[p] * is2;
    }
    __syncthreads();

    // weighted path combine for tokens [tbase, tbase+64)
    const size_t v0 = (size_t)tbase * 512;        // float4 index base
#pragma unroll 2
    for (int it = 0; it < 128; it++) {
        const int idx = it * 256 + tid;           // 0 .. 32767
        const size_t v = v0 + idx;
        const int tt = idx >> 9;                  // local token 0..63
        const int h  = (idx >> 5) & 15;
        const float* pb = lg + tt * OUT_DIM + h * NP;
        const float w0 = pb[0], w1 = pb[1], w2 = pb[2], w3 = pb[3], w4 = pb[4];
        const float4 a0 = reinterpret_cast<const float4*>(p0)[v];
        const float4 a1 = reinterpret_cast<const float4*>(p1)[v];
        const float4 a2 = reinterpret_cast<const float4*>(p2)[v];
        const float4 a3 = reinterpret_cast<const float4*>(p3)[v];
        const float4 a4 = reinterpret_cast<const float4*>(p4)[v];
        float4 o;
        o.x = a0.x * w0 + a1.x * w1 + a2.x * w2 + a3.x * w3 + a4.x * w4;
        o.y = a0.y * w0 + a1.y * w1 + a2.y * w2 + a3.y * w3 + a4.y * w4;
        o.z = a0.z * w0 + a1.z * w1 + a2.z * w2 + a3.z * w3 + a4.z * w4;
        o.w = a0.w * w0 + a1.w * w1 + a2.w * w2 + a3.w * w3 + a4.w * w4;
        reinterpret_cast<float4*>(out)[v] = o;
    }
}

// ---------------------------------------------------------------------------
extern "C" void kernel_launch(void* const* d_in, const int* in_sizes, int n_in,
                              void* d_out, int out_size)
{
    const float* hidden = (const float*)d_in[0];
    const float* p0 = (const float*)d_in[1];
    const float* p1 = (const float*)d_in[2];
    const float* p2 = (const float*)d_in[3];
    const float* p3 = (const float*)d_in[4];
    const float* p4 = (const float*)d_in[5];
    const float* W1 = (const float*)d_in[6];
    const float* b1 = (const float*)d_in[7];
    const float* W2 = (const float*)d_in[8];
    const float* b2 = (const float*)d_in[9];
    const float* lt = (const float*)d_in[10];

    const int NT = in_sizes[0] / HIDDEN;   // 8192

    static int smem_set = 0;
    if (!smem_set) {
        cudaFuncSetAttribute(gemm1_mma_kernel,
                             cudaFuncAttributeMaxDynamicSharedMemorySize, GEMM1_SMEM);
        cudaFuncSetAttribute(epi_kernel,
                             cudaFuncAttributeMaxDynamicSharedMemorySize, EPI_SMEM);
        smem_set = 1;
    }

    const int nout = NT * NH * HD;

    // 1) fused prep
    fused_prep_kernel<<<NB_TOTAL, 512>>>(hidden, p0, p1, p2, p3, p4,
                                         W1, W2, (float*)d_out, nout, out_size);

    cudaLaunchAttribute attr[1];
    attr[0].id = cudaLaunchAttributeProgrammaticStreamSerialization;
    attr[0].val.programmaticStreamSerializationAllowed = 1;

    // 2) gemm1 — PSS over prep; triggers epi at start; publishes M-blocks
    {
        cudaLaunchConfig_t cfg = {};
        cfg.gridDim = dim3(GATE_HID / 256, NT / 128);
        cfg.blockDim = dim3(256);
        cfg.dynamicSmemBytes = GEMM1_SMEM;
        cfg.stream = 0;
        cfg.attrs = attr;
        cfg.numAttrs = 1;
        cudaLaunchKernelEx(&cfg, gemm1_mma_kernel, b1);
    }

    // 3) epi — PSS over gemm1 (launches during gemm1, co-resident); spins per
    //    M-block, then gemm2+softmax+output for its 64 tokens.
    {
        cudaLaunchConfig_t cfg = {};
        cfg.gridDim = dim3(NT / 64);
        cfg.blockDim = dim3(256);
        cfg.dynamicSmemBytes = EPI_SMEM;
        cfg.stream = 0;
        cfg.attrs = attr;
        cfg.numAttrs = 1;
        cudaLaunchKernelEx(&cfg, epi_kernel, b2, lt, p0, p1, p2, p3, p4, (float*)d_out);
    }
}

// round 16
// speedup vs baseline: 1.4503x; 1.4503x over previous
#include <cuda_runtime.h>
#include <cuda_fp16.h>
#include <cstdint>
#include <math.h>

#define HIDDEN      2048
#define GATE_IN     2608
#define GATE_IN_PAD 2624        // 41 * 64
#define STAT_W      576         // 560 data + 16 zero pad (halves)
#define GATE_HID    1024
#define NH          16
#define HD          128
#define NP          5
#define OUT_DIM     80
#define MAX_NT      8192

// GEMM1: CTA 128x256, 8 warps (2M x 4N, warp 64x64), fp16 m16n8k16 + ldmatrix
#define KCH         64                         // halves per K chunk (128 B)
#define NCHUNK      (GATE_IN_PAD / KCH)        // 41
#define STRH        72                         // padded halves per row
#define G1_A_H      (128 * STRH)
#define G1_B_H      (256 * STRH)
#define G1_STAGE_B  ((G1_A_H + G1_B_H) * 2)    // 55296 B
#define GEMM1_SMEM  (3 * G1_STAGE_B)           // 165888 B

// GEMM2: CTA 64(M) x 80(N), 8 warps (4M x 2N, warp 16x40), K=1024
#define G2_NCH      (GATE_HID / KCH)           // 16
#define G2_A_H      (64 * STRH)
#define G2_B_H      (80 * STRH)
#define GEMM2_SMEM  (2 * (G2_A_H + G2_B_H) * 2)

// fused prep grid layout (1 token per stats CTA)
#define NB_STATS    MAX_NT                     // 8192
#define NB_W1       656
#define NB_W2       20
#define NB_TOTAL    (NB_STATS + NB_W1 + NB_W2 + 1)

// Static scratch (fp16 operands)
__device__ __half g_hid_h[(size_t)MAX_NT * HIDDEN];
__device__ __half g_stats[(size_t)MAX_NT * STAT_W];
__device__ __half g_w1p[(size_t)GATE_HID * GATE_IN_PAD];
__device__ __half g_w2p[(size_t)OUT_DIM * GATE_HID];
__device__ __half g_h[(size_t)MAX_NT * GATE_HID];
__device__ float  g_probs[(size_t)MAX_NT * OUT_DIM];

// ---------------------------------------------------------------------------
// helpers
// ---------------------------------------------------------------------------
__device__ __forceinline__ float wredsum(float v) {
#pragma unroll
    for (int o = 16; o; o >>= 1) v += __shfl_xor_sync(0xffffffffu, v, o);
    return v;
}
__device__ __forceinline__ void cp_async16(uint32_t dst, const void* src) {
    asm volatile("cp.async.cg.shared.global [%0], [%1], 16;" :: "r"(dst), "l"(src));
}
__device__ __forceinline__ uint32_t smem_u32(const void* p) {
    uint32_t a;
    asm("{ .reg .u64 t; cvta.to.shared.u64 t, %1; cvt.u32.u64 %0, t; }" : "=r"(a) : "l"(p));
    return a;
}
__device__ __forceinline__ float gelu(float x) {
    return 0.5f * x * (1.0f + erff(x * 0.70710678118654752f));
}
__device__ __forceinline__ void ldmatrix_x4(uint32_t r[4], uint32_t addr) {
    asm volatile("ldmatrix.sync.aligned.m8n8.x4.shared.b16 {%0,%1,%2,%3}, [%4];"
                 : "=r"(r[0]), "=r"(r[1]), "=r"(r[2]), "=r"(r[3]) : "r"(addr));
}
#define GDC_TRIGGER() asm volatile("griddepcontrol.launch_dependents;" ::: "memory")
#define GDC_WAIT()    asm volatile("griddepcontrol.wait;" ::: "memory")
// m16n8k16 f16, fp32 accum. c0=(g,2t) c1=(g,2t+1) c2=(g+8,2t) c3=(g+8,2t+1)
__device__ __forceinline__ void mma_f16_16x8x16(float c[4],
                                                uint32_t a0, uint32_t a1,
                                                uint32_t a2, uint32_t a3,
                                                uint32_t b0, uint32_t b1) {
    asm("mma.sync.aligned.m16n8k16.row.col.f32.f16.f16.f32 "
        "{%0,%1,%2,%3}, {%4,%5,%6,%7}, {%8,%9}, {%0,%1,%2,%3};"
        : "+f"(c[0]), "+f"(c[1]), "+f"(c[2]), "+f"(c[3])
        : "r"(a0), "r"(a1), "r"(a2), "r"(a3), "r"(b0), "r"(b1));
}

__device__ __forceinline__ uint2 f4_to_h4(float4 v) {
    __half2 h0 = __floats2half2_rn(v.x, v.y);
    __half2 h1 = __floats2half2_rn(v.z, v.w);
    uint2 u;
    u.x = *reinterpret_cast<uint32_t*>(&h0);
    u.y = *reinterpret_cast<uint32_t*>(&h1);
    return u;
}

// ---------------------------------------------------------------------------
// Fused prep+stats kernel, 512 threads, 1 token per stats CTA.
//   bid < 8192:             stats + hidden fp16 for token bid
//   [8192, 8848):           W1 pack
//   [8848, 8868):           W2 pack
//   8868:                   output tail zero
// ---------------------------------------------------------------------------
__global__ void __launch_bounds__(512) fused_prep_kernel(
    const float* __restrict__ hidden,
    const float* __restrict__ p0, const float* __restrict__ p1,
    const float* __restrict__ p2, const float* __restrict__ p3,
    const float* __restrict__ p4,
    const float* __restrict__ W1, const float* __restrict__ W2,
    float* __restrict__ out, int tail_start, int out_total)
{
    const int bid = blockIdx.x, tid = threadIdx.x;

    if (bid >= NB_STATS) {
        const int pb = bid - NB_STATS;
        if (pb < NB_W1) {
#pragma unroll
            for (int j = 0; j < 2; j++) {
                const int idx = pb * 1024 + tid + j * 512;     // 4-half group
                const int row = idx / (GATE_IN_PAD / 4);
                const int c4  = idx % (GATE_IN_PAD / 4);
                float4 v = {0.f, 0.f, 0.f, 0.f};
                if (c4 < GATE_IN / 4)
                    v = reinterpret_cast<const float4*>(W1 + (size_t)row * GATE_IN)[c4];
                reinterpret_cast<uint2*>(g_w1p + (size_t)row * GATE_IN_PAD)[c4] = f4_to_h4(v);
            }
        } else if (pb < NB_W1 + NB_W2) {
#pragma unroll
            for (int j = 0; j < 2; j++) {
                const int idx = (pb - NB_W1) * 1024 + tid + j * 512;   // < 20480
                float4 v = reinterpret_cast<const float4*>(W2)[idx];
                reinterpret_cast<uint2*>(g_w2p)[idx] = f4_to_h4(v);
            }
        } else {
            for (int i = tail_start + tid; i < out_total; i += 512) out[i] = 0.0f;
        }
        return;
    }

    // ---- stats for token bid ----
    const int t = bid;
    __half* gate = g_stats + (size_t)t * STAT_W;

    {   // hidden fp32 -> fp16
        const float4 hv = (reinterpret_cast<const float4*>(hidden) + (size_t)t * (HIDDEN / 4))[tid];
        reinterpret_cast<uint2*>(g_hid_h + (size_t)t * HIDDEN)[tid] = f4_to_h4(hv);
    }
    if (tid < 4) {
        uint2 z = {0u, 0u};
        reinterpret_cast<uint2*>(gate + 560)[tid] = z;
    }

    const int w = tid >> 5, lane = tid & 31;
    const float* pp[NP] = {p0, p1, p2, p3, p4};
    const size_t base = (size_t)t * (NH * HD) + (size_t)w * HD + lane * 4;

    float4 v[NP];
#pragma unroll
    for (int p = 0; p < NP; p++) v[p] = *reinterpret_cast<const float4*>(pp[p] + base);

    float vals[25];
#pragma unroll
    for (int p = 0; p < NP; p++) {
        vals[p]      = v[p].x + v[p].y + v[p].z + v[p].w;
        vals[5 + p]  = v[p].x * v[p].x + v[p].y * v[p].y + v[p].z * v[p].z + v[p].w * v[p].w;
        vals[10 + p] = fabsf(v[p].x) + fabsf(v[p].y) + fabsf(v[p].z) + fabsf(v[p].w);
    }
    {
        int k = 15;
#pragma unroll
        for (int p = 0; p < NP; p++)
#pragma unroll
            for (int q = p + 1; q < NP; q++)
                vals[k++] = v[p].x * v[q].x + v[p].y * v[q].y + v[p].z * v[q].z + v[p].w * v[q].w;
    }
#pragma unroll
    for (int i = 0; i < 25; i++) vals[i] = wredsum(vals[i]);

    if (lane == 0) {
        const float inv = 1.0f / 128.0f;
        float sq[NP];
#pragma unroll
        for (int p = 0; p < NP; p++) {
            float mean = vals[p] * inv;
            sq[p] = vals[5 + p];
            float l2 = sqrtf(sq[p]);
            float var = sq[p] * inv - mean * mean;
            float am  = vals[10 + p] * inv;
            __half* s = gate + w * (NP * 4) + p * 4;
            s[0] = __float2half_rn(mean); s[1] = __float2half_rn(var);
            s[2] = __float2half_rn(am);   s[3] = __float2half_rn(l2);
            gate[320 + w * NP + p] = __float2half_rn(l2);
        }
        int kk = 0;
#pragma unroll
        for (int p = 0; p < NP; p++)
#pragma unroll
            for (int q = p + 1; q < NP; q++) {
                float d2 = sq[p] + sq[q] - 2.0f * vals[15 + kk];
                gate[400 + w * 10 + kk] = __float2half_rn(sqrtf(fmaxf(d2, 0.0f)));
                kk++;
            }
    }
}

// ---------------------------------------------------------------------------
// GEMM1 fp16 mma + ldmatrix (R9 body), PDL consumer over fused prep.
// ---------------------------------------------------------------------------
__device__ __forceinline__ void g1_load(uint32_t stage_s,
                                        const __half* __restrict__ hid,
                                        const __half* __restrict__ st,
                                        const __half* __restrict__ Bm,
                                        int k0, int tid)
{
    const uint32_t a_s = stage_s;
    const uint32_t b_s = stage_s + G1_A_H * 2;
    const __half* asrc;
    int astride, ak;
    if (k0 < HIDDEN) { asrc = hid; astride = HIDDEN; ak = k0; }
    else             { asrc = st;  astride = STAT_W; ak = k0 - HIDDEN; }
#pragma unroll
    for (int j = 0; j < 4; j++) {
        const int idx = tid + j * 256;
        const int m  = idx >> 3;
        const int ks = (idx & 7) << 3;
        cp_async16(a_s + (uint32_t)(m * STRH + ks) * 2,
                   asrc + (size_t)m * astride + ak + ks);
    }
#pragma unroll
    for (int j = 0; j < 8; j++) {
        const int idx = tid + j * 256;
        const int m  = idx >> 3;
        const int ks = (idx & 7) << 3;
        cp_async16(b_s + (uint32_t)(m * STRH + ks) * 2,
                   Bm + (size_t)m * GATE_IN_PAD + k0 + ks);
    }
}

__global__ void __launch_bounds__(256, 1) gemm1_mma_kernel(const float* __restrict__ b1)
{
    GDC_WAIT();   // fused prep must be complete before any reads

    extern __shared__ __half smem[];
    const uint32_t s0 = smem_u32(smem);

    const int tid  = threadIdx.x;
    const int wid  = tid >> 5, lane = tid & 31;
    const int wm   = (wid & 1) * 64;
    const int wn   = (wid >> 1) * 64;
    const int g    = lane >> 2;
    const int t2   = (lane & 3) * 2;
    const int quad = lane >> 3;

    const uint32_t a_loff = (uint32_t)(((quad & 1) * 8 + (lane & 7)) * STRH + (quad >> 1) * 8);
    const uint32_t b_loff = (uint32_t)(((quad >> 1) * 8 + (lane & 7)) * STRH + (quad & 1) * 8);

    const __half* hid = g_hid_h + (size_t)blockIdx.y * 128 * HIDDEN;
    const __half* st  = g_stats + (size_t)blockIdx.y * 128 * STAT_W;
    const __half* Bm  = g_w1p   + (size_t)blockIdx.x * 256 * GATE_IN_PAD;

    float acc[4][8][4];
#pragma unroll
    for (int i = 0; i < 4; i++)
#pragma unroll
        for (int j = 0; j < 8; j++)
#pragma unroll
            for (int r = 0; r < 4; r++) acc[i][j][r] = 0.0f;

    g1_load(s0, hid, st, Bm, 0, tid);
    asm volatile("cp.async.commit_group;" ::: "memory");
    g1_load(s0 + G1_STAGE_B, hid, st, Bm, KCH, tid);
    asm volatile("cp.async.commit_group;" ::: "memory");

    int stage_rd = 0;
    for (int i = 0; i < NCHUNK; i++) {
        if (i + 2 < NCHUNK) {
            const int ws = (i + 2) % 3;
            g1_load(s0 + (uint32_t)ws * G1_STAGE_B, hid, st, Bm, (i + 2) * KCH, tid);
        }
        asm volatile("cp.async.commit_group;" ::: "memory");
        asm volatile("cp.async.wait_group 2;" ::: "memory");
        __syncthreads();

        const uint32_t as_u = s0 + (uint32_t)stage_rd * G1_STAGE_B;
        const uint32_t bs_u = as_u + G1_A_H * 2;

#pragma unroll
        for (int kk = 0; kk < KCH; kk += 16) {
            uint32_t a[4][4];
#pragma unroll
            for (int mi = 0; mi < 4; mi++)
                ldmatrix_x4(a[mi],
                            as_u + ((uint32_t)((wm + mi * 16) * STRH + kk) + a_loff) * 2);
            uint32_t b[4][4];
#pragma unroll
            for (int njp = 0; njp < 4; njp++)
                ldmatrix_x4(b[njp],
                            bs_u + ((uint32_t)((wn + njp * 16) * STRH + kk) + b_loff) * 2);
#pragma unroll
            for (int mi = 0; mi < 4; mi++)
#pragma unroll
                for (int njp = 0; njp < 4; njp++) {
                    mma_f16_16x8x16(acc[mi][njp * 2],     a[mi][0], a[mi][1], a[mi][2], a[mi][3],
                                    b[njp][0], b[njp][1]);
                    mma_f16_16x8x16(acc[mi][njp * 2 + 1], a[mi][0], a[mi][1], a[mi][2], a[mi][3],
                                    b[njp][2], b[njp][3]);
                }
        }
        __syncthreads();
        stage_rd = stage_rd + 1 == 3 ? 0 : stage_rd + 1;
    }

    const size_t row_base = (size_t)blockIdx.y * 128 + wm + g;
    const int    col_base = blockIdx.x * 256 + wn + t2;
#pragma unroll
    for (int nj = 0; nj < 8; nj++) {
        const int gc = col_base + nj * 8;
        const float2 bb = *reinterpret_cast<const float2*>(b1 + gc);
#pragma unroll
        for (int mi = 0; mi < 4; mi++) {
            const size_t r0 = row_base + mi * 16;
            __half2 o0 = __floats2half2_rn(gelu(acc[mi][nj][0] + bb.x),
                                           gelu(acc[mi][nj][1] + bb.y));
            __half2 o1 = __floats2half2_rn(gelu(acc[mi][nj][2] + bb.x),
                                           gelu(acc[mi][nj][3] + bb.y));
            *reinterpret_cast<__half2*>(g_h + r0 * GATE_HID + gc)       = o0;
            *reinterpret_cast<__half2*>(g_h + (r0 + 8) * GATE_HID + gc) = o1;
        }
    }
}

// ---------------------------------------------------------------------------
// GEMM2 fp16 mma + fused bias/softmax/clip/renorm (PDL producer+consumer).
// ---------------------------------------------------------------------------
__global__ void __launch_bounds__(256) gemm2_mma_kernel(
    const float* __restrict__ b2, const float* __restrict__ log_temp)
{
    GDC_TRIGGER();
    GDC_WAIT();

    extern __shared__ __half smem[];
    const uint32_t s0 = smem_u32(smem);

    const int tid  = threadIdx.x;
    const int wid  = tid >> 5, lane = tid & 31;
    const int mw   = wid >> 1;
    const int nw   = wid & 1;
    const int g    = lane >> 2;
    const int t2   = (lane & 3) * 2;

    const int tbase = blockIdx.x * 64;
    const __half* A = g_h + (size_t)tbase * GATE_HID;

    float acc[5][4];
#pragma unroll
    for (int j = 0; j < 5; j++)
#pragma unroll
        for (int r = 0; r < 4; r++) acc[j][r] = 0.0f;

    const uint32_t aoff[2] = {0u, (uint32_t)G2_A_H * 2};
    const uint32_t boff[2] = {(uint32_t)(2 * G2_A_H) * 2,
                              (uint32_t)(2 * G2_A_H + G2_B_H) * 2};

    {
#pragma unroll
        for (int j = 0; j < 2; j++) {
            const int idx = tid + j * 256;
            const int m = idx >> 3, ks = (idx & 7) << 3;
            cp_async16(s0 + aoff[0] + (uint32_t)(m * STRH + ks) * 2,
                       A + (size_t)m * GATE_HID + ks);
        }
#pragma unroll
        for (int j = 0; j < 3; j++) {
            const int idx = tid + j * 256;
            if (idx < 640) {
                const int m = idx >> 3, ks = (idx & 7) << 3;
                cp_async16(s0 + boff[0] + (uint32_t)(m * STRH + ks) * 2,
                           g_w2p + (size_t)m * GATE_HID + ks);
            }
        }
        asm volatile("cp.async.commit_group;" ::: "memory");
    }

    for (int i = 0; i < G2_NCH; i++) {
        const int s = i & 1;
        if (i + 1 < G2_NCH) {
            const int ns = (i + 1) & 1;
            const int k0 = (i + 1) * KCH;
#pragma unroll
            for (int j = 0; j < 2; j++) {
                const int idx = tid + j * 256;
                const int m = idx >> 3, ks = (idx & 7) << 3;
                cp_async16(s0 + aoff[ns] + (uint32_t)(m * STRH + ks) * 2,
                           A + (size_t)m * GATE_HID + k0 + ks);
            }
#pragma unroll
            for (int j = 0; j < 3; j++) {
                const int idx = tid + j * 256;
                if (idx < 640) {
                    const int m = idx >> 3, ks = (idx & 7) << 3;
                    cp_async16(s0 + boff[ns] + (uint32_t)(m * STRH + ks) * 2,
                               g_w2p + (size_t)m * GATE_HID + k0 + ks);
                }
            }
        }
        asm volatile("cp.async.commit_group;" ::: "memory");
        if (i + 1 < G2_NCH) asm volatile("cp.async.wait_group 1;" ::: "memory");
        else                asm volatile("cp.async.wait_group 0;" ::: "memory");
        __syncthreads();

        const __half* as = smem + (s ? G2_A_H : 0);
        const __half* bs = smem + 2 * G2_A_H + (s ? G2_B_H : 0);

#pragma unroll
        for (int kk = 0; kk < KCH; kk += 16) {
            const __half* r0 = as + (mw * 16 + g) * STRH + kk + t2;
            const __half* r1 = as + (mw * 16 + g + 8) * STRH + kk + t2;
            uint32_t a0 = *reinterpret_cast<const uint32_t*>(r0);
            uint32_t a1 = *reinterpret_cast<const uint32_t*>(r1);
            uint32_t a2 = *reinterpret_cast<const uint32_t*>(r0 + 8);
            uint32_t a3 = *reinterpret_cast<const uint32_t*>(r1 + 8);
#pragma unroll
            for (int nj = 0; nj < 5; nj++) {
                const __half* br = bs + (nw * 40 + nj * 8 + g) * STRH + kk + t2;
                mma_f16_16x8x16(acc[nj], a0, a1, a2, a3,
                                *reinterpret_cast<const uint32_t*>(br),
                                *reinterpret_cast<const uint32_t*>(br + 8));
            }
        }
        __syncthreads();
    }

    float* lg = reinterpret_cast<float*>(smem);
    {
        const int r0 = mw * 16 + g;
        const int c0 = nw * 40 + t2;
#pragma unroll
        for (int nj = 0; nj < 5; nj++) {
            const int c = c0 + nj * 8;
            lg[r0 * OUT_DIM + c]            = acc[nj][0];
            lg[r0 * OUT_DIM + c + 1]        = acc[nj][1];
            lg[(r0 + 8) * OUT_DIM + c]      = acc[nj][2];
            lg[(r0 + 8) * OUT_DIM + c + 1]  = acc[nj][3];
        }
    }
    __syncthreads();

#pragma unroll
    for (int it = 0; it < 4; it++) {
        const int idx = tid + it * 256;
        const int tt = idx >> 4, h = idx & 15;
        const float invt = expf(-log_temp[h]);
        float l[NP], mx = -1e30f;
#pragma unroll
        for (int p = 0; p < NP; p++) {
            l[p] = (lg[tt * OUT_DIM + h * NP + p] + __ldg(b2 + h * NP + p)) * invt;
            mx = fmaxf(mx, l[p]);
        }
        float e[NP], se = 0.f;
#pragma unroll
        for (int p = 0; p < NP; p++) { e[p] = expf(l[p] - mx); se += e[p]; }
        const float ise = 1.0f / se;
        float pr[NP], s2s = 0.f;
#pragma unroll
        for (int p = 0; p < NP; p++) { pr[p] = fmaxf(e[p] * ise, 0.02f); s2s += pr[p]; }
        const float is2 = 1.0f / s2s;
        float* dst = g_probs + (size_t)(tbase + tt) * OUT_DIM + h * NP;
#pragma unroll
        for (int p = 0; p < NP; p++) dst[p] = pr[p] * is2;
    }
}

// ---------------------------------------------------------------------------
// Output: PDL consumer — prefetch path data BEFORE waiting on gemm2's probs.
// ---------------------------------------------------------------------------
__global__ void __launch_bounds__(256) output_kernel(
    const float* __restrict__ p0, const float* __restrict__ p1,
    const float* __restrict__ p2, const float* __restrict__ p3,
    const float* __restrict__ p4, float* __restrict__ out, int n4)
{
    const int v = blockIdx.x * blockDim.x + threadIdx.x;
    if (v >= n4) { GDC_WAIT(); return; }
    const int t = v >> 9;
    const int h = (v >> 5) & 15;
    const float4 a0 = reinterpret_cast<const float4*>(p0)[v];
    const float4 a1 = reinterpret_cast<const float4*>(p1)[v];
    const float4 a2 = reinterpret_cast<const float4*>(p2)[v];
    const float4 a3 = reinterpret_cast<const float4*>(p3)[v];
    const float4 a4 = reinterpret_cast<const float4*>(p4)[v];
    GDC_WAIT();
    const float* pb = g_probs + (size_t)t * OUT_DIM + h * NP;
    const float w0 = pb[0], w1 = pb[1], w2 = pb[2], w3 = pb[3], w4 = pb[4];
    float4 o;
    o.x = a0.x * w0 + a1.x * w1 + a2.x * w2 + a3.x * w3 + a4.x * w4;
    o.y = a0.y * w0 + a1.y * w1 + a2.y * w2 + a3.y * w3 + a4.y * w4;
    o.z = a0.z * w0 + a1.z * w1 + a2.z * w2 + a3.z * w3 + a4.z * w4;
    o.w = a0.w * w0 + a1.w * w1 + a2.w * w2 + a3.w * w3 + a4.w * w4;
    reinterpret_cast<float4*>(out)[v] = o;
}

// ---------------------------------------------------------------------------
extern "C" void kernel_launch(void* const* d_in, const int* in_sizes, int n_in,
                              void* d_out, int out_size)
{
    const float* hidden = (const float*)d_in[0];
    const float* p0 = (const float*)d_in[1];
    const float* p1 = (const float*)d_in[2];
    const float* p2 = (const float*)d_in[3];
    const float* p3 = (const float*)d_in[4];
    const float* p4 = (const float*)d_in[5];
    const float* W1 = (const float*)d_in[6];
    const float* b1 = (const float*)d_in[7];
    const float* W2 = (const float*)d_in[8];
    const float* b2 = (const float*)d_in[9];
    const float* lt = (const float*)d_in[10];

    const int NT = in_sizes[0] / HIDDEN;   // 8192

    static int smem_set = 0;
    if (!smem_set) {
        cudaFuncSetAttribute(gemm1_mma_kernel,
                             cudaFuncAttributeMaxDynamicSharedMemorySize, GEMM1_SMEM);
        cudaFuncSetAttribute(gemm2_mma_kernel,
                             cudaFuncAttributeMaxDynamicSharedMemorySize, GEMM2_SMEM);
        smem_set = 1;
    }

    const int nout = NT * NH * HD;

    // 1) fused prep: stats (1 tok/CTA) + hidden convert + W packs + tail zero
    fused_prep_kernel<<<NB_TOTAL, 512>>>(hidden, p0, p1, p2, p3, p4,
                                         W1, W2, (float*)d_out, nout, out_size);

    cudaLaunchAttribute attr[1];
    attr[0].id = cudaLaunchAttributeProgrammaticStreamSerialization;
    attr[0].val.programmaticStreamSerializationAllowed = 1;

    // 2) gemm1 — PSS over prep (hides launch latency; waits at kernel top)
    {
        cudaLaunchConfig_t cfg = {};
        cfg.gridDim = dim3(GATE_HID / 256, NT / 128);   // (4, 64)
        cfg.blockDim = dim3(256);
        cfg.dynamicSmemBytes = GEMM1_SMEM;
        cfg.stream = 0;
        cfg.attrs = attr;
        cfg.numAttrs = 1;
        cudaLaunchKernelEx(&cfg, gemm1_mma_kernel, b1);
    }

    // 3) gemm2 — PSS over gemm1, triggers early for output
    {
        cudaLaunchConfig_t cfg = {};
        cfg.gridDim = dim3(NT / 64);
        cfg.blockDim = dim3(256);
        cfg.dynamicSmemBytes = GEMM2_SMEM;
        cfg.stream = 0;
        cfg.attrs = attr;
        cfg.numAttrs = 1;
        cudaLaunchKernelEx(&cfg, gemm2_mma_kernel, b2, lt);
    }

    // 4) output — PSS over gemm2; prefetches paths before waiting on probs
    {
        const int n4 = NT * (NH * HD) / 4;
        cudaLaunchConfig_t cfg = {};
        cfg.gridDim = dim3((n4 + 255) / 256);
        cfg.blockDim = dim3(256);
        cfg.dynamicSmemBytes = 0;
        cfg.stream = 0;
        cfg.attrs = attr;
        cfg.numAttrs = 1;
        cudaLaunchKernelEx(&cfg, output_kernel, p0, p1, p2, p3, p4, (float*)d_out, n4);
    }
}

// round 17
// speedup vs baseline: 1.5853x; 1.0932x over previous
#include <cuda_runtime.h>
#include <cuda_fp16.h>
#include <cstdint>
#include <math.h>

#define HIDDEN      2048
#define GATE_IN     2608
#define GATE_IN_PAD 2624        // 41 * 64
#define STAT_W      576         // 560 data + 16 zero pad (halves)
#define GATE_HID    1024
#define NH          16
#define HD          128
#define NP          5
#define OUT_DIM     80
#define MAX_NT      8192

// GEMM1: CTA 128x256, 8 warps (2M x 4N, warp 64x64), fp16 m16n8k16 + ldmatrix
#define KCH         64                         // halves per K chunk (128 B)
#define NCHUNK      (GATE_IN_PAD / KCH)        // 41
#define STRH        72                         // padded halves per row
#define G1_A_H      (128 * STRH)
#define G1_B_H      (256 * STRH)
#define G1_STAGE_B  ((G1_A_H + G1_B_H) * 2)    // 55296 B
#define GEMM1_SMEM  (3 * G1_STAGE_B)           // 165888 B

// GEMM2: CTA 64(M) x 80(N), 8 warps (4M x 2N, warp 16x40), K=1024
#define G2_NCH      (GATE_HID / KCH)           // 16
#define G2_A_H      (64 * STRH)
#define G2_B_H      (80 * STRH)
#define GEMM2_SMEM  (2 * (G2_A_H + G2_B_H) * 2)

// fused prep grid layout: 128-thread CTAs
//   stats: 1 token per CTA (4 warps x 4 heads, 8-lane reduction groups)
//   W1 pack: 512 groups/CTA -> 1312 CTAs ; W2: 40 CTAs ; tail: 1 CTA
#define NB_STATS    MAX_NT                     // 8192
#define NB_W1       1312
#define NB_W2       40
#define NB_TOTAL    (NB_STATS + NB_W1 + NB_W2 + 1)

// Static scratch (fp16 operands)
__device__ __half g_hid_h[(size_t)MAX_NT * HIDDEN];
__device__ __half g_stats[(size_t)MAX_NT * STAT_W];
__device__ __half g_w1p[(size_t)GATE_HID * GATE_IN_PAD];
__device__ __half g_w2p[(size_t)OUT_DIM * GATE_HID];
__device__ __half g_h[(size_t)MAX_NT * GATE_HID];
__device__ float  g_probs[(size_t)MAX_NT * OUT_DIM];

// ---------------------------------------------------------------------------
// helpers
// ---------------------------------------------------------------------------
__device__ __forceinline__ void cp_async16(uint32_t dst, const void* src) {
    asm volatile("cp.async.cg.shared.global [%0], [%1], 16;" :: "r"(dst), "l"(src));
}
__device__ __forceinline__ uint32_t smem_u32(const void* p) {
    uint32_t a;
    asm("{ .reg .u64 t; cvta.to.shared.u64 t, %1; cvt.u32.u64 %0, t; }" : "=r"(a) : "l"(p));
    return a;
}
__device__ __forceinline__ float gelu(float x) {
    return 0.5f * x * (1.0f + erff(x * 0.70710678118654752f));
}
__device__ __forceinline__ void ldmatrix_x4(uint32_t r[4], uint32_t addr) {
    asm volatile("ldmatrix.sync.aligned.m8n8.x4.shared.b16 {%0,%1,%2,%3}, [%4];"
                 : "=r"(r[0]), "=r"(r[1]), "=r"(r[2]), "=r"(r[3]) : "r"(addr));
}
#define GDC_TRIGGER() asm volatile("griddepcontrol.launch_dependents;" ::: "memory")
#define GDC_WAIT()    asm volatile("griddepcontrol.wait;" ::: "memory")
// m16n8k16 f16, fp32 accum. c0=(g,2t) c1=(g,2t+1) c2=(g+8,2t) c3=(g+8,2t+1)
__device__ __forceinline__ void mma_f16_16x8x16(float c[4],
                                                uint32_t a0, uint32_t a1,
                                                uint32_t a2, uint32_t a3,
                                                uint32_t b0, uint32_t b1) {
    asm("mma.sync.aligned.m16n8k16.row.col.f32.f16.f16.f32 "
        "{%0,%1,%2,%3}, {%4,%5,%6,%7}, {%8,%9}, {%0,%1,%2,%3};"
        : "+f"(c[0]), "+f"(c[1]), "+f"(c[2]), "+f"(c[3])
        : "r"(a0), "r"(a1), "r"(a2), "r"(a3), "r"(b0), "r"(b1));
}
__device__ __forceinline__ uint2 f4_to_h4(float4 v) {
    __half2 h0 = __floats2half2_rn(v.x, v.y);
    __half2 h1 = __floats2half2_rn(v.z, v.w);
    uint2 u;
    u.x = *reinterpret_cast<uint32_t*>(&h0);
    u.y = *reinterpret_cast<uint32_t*>(&h1);
    return u;
}

// ---------------------------------------------------------------------------
// Fused prep+stats kernel, 128 threads.
//   bid < 8192:               stats + hidden fp16 for token bid
//   [8192, 8192+1312):        W1 pack (512 groups/CTA)
//   [.., +40):                W2 pack
//   last:                     output tail zero
// Stats: 4 warps; warp w handles heads w*4+g (g = lane>>3); 8-lane groups,
// 16 elems/lane/path accumulated in registers, 3-stage butterfly (75 SHFL
// per warp for 4 heads vs 125/head in the 32-lane version).
// ---------------------------------------------------------------------------
__global__ void __launch_bounds__(128) fused_prep_kernel(
    const float* __restrict__ hidden,
    const float* __restrict__ p0, const float* __restrict__ p1,
    const float* __restrict__ p2, const float* __restrict__ p3,
    const float* __restrict__ p4,
    const float* __restrict__ W1, const float* __restrict__ W2,
    float* __restrict__ out, int tail_start, int out_total)
{
    const int bid = blockIdx.x, tid = threadIdx.x;

    if (bid >= NB_STATS) {
        const int pb = bid - NB_STATS;
        if (pb < NB_W1) {
#pragma unroll
            for (int j = 0; j < 4; j++) {
                const int idx = pb * 512 + tid + j * 128;      // 4-half group
                const int row = idx / (GATE_IN_PAD / 4);
                const int c4  = idx % (GATE_IN_PAD / 4);
                float4 v = {0.f, 0.f, 0.f, 0.f};
                if (c4 < GATE_IN / 4)
                    v = reinterpret_cast<const float4*>(W1 + (size_t)row * GATE_IN)[c4];
                reinterpret_cast<uint2*>(g_w1p + (size_t)row * GATE_IN_PAD)[c4] = f4_to_h4(v);
            }
        } else if (pb < NB_W1 + NB_W2) {
#pragma unroll
            for (int j = 0; j < 4; j++) {
                const int idx = (pb - NB_W1) * 512 + tid + j * 128;   // < 20480
                float4 v = reinterpret_cast<const float4*>(W2)[idx];
                reinterpret_cast<uint2*>(g_w2p)[idx] = f4_to_h4(v);
            }
        } else {
            for (int i = tail_start + tid; i < out_total; i += 128) out[i] = 0.0f;
        }
        return;
    }

    // ---- stats for token bid ----
    const int t = bid;
    __half* gate = g_stats + (size_t)t * STAT_W;

    {   // hidden fp32 -> fp16 (128 threads x 4 float4)
        const float4* hsrc = reinterpret_cast<const float4*>(hidden) + (size_t)t * (HIDDEN / 4);
        uint2* hdst = reinterpret_cast<uint2*>(g_hid_h + (size_t)t * HIDDEN);
#pragma unroll
        for (int j = 0; j < 4; j++) {
            const int idx = tid + j * 128;
            hdst[idx] = f4_to_h4(hsrc[idx]);
        }
    }
    if (tid < 4) {   // zero pad halves [560:576)
        uint2 z = {0u, 0u};
        reinterpret_cast<uint2*>(gate + 560)[tid] = z;
    }

    const int w    = tid >> 5, lane = tid & 31;
    const int grp  = lane >> 3;          // 0..3: head sub-group within warp
    const int gl   = lane & 7;           // lane within 8-lane group
    const int h    = w * 4 + grp;        // head 0..15
    const float* pp[NP] = {p0, p1, p2, p3, p4};

    float acc[25];
#pragma unroll
    for (int i = 0; i < 25; i++) acc[i] = 0.0f;

    const size_t base = (size_t)t * (NH * HD) + (size_t)h * HD + gl * 4;
#pragma unroll
    for (int it = 0; it < 4; it++) {
        const size_t off = base + it * 32;
        float4 v[NP];
#pragma unroll
        for (int p = 0; p < NP; p++) v[p] = *reinterpret_cast<const float4*>(pp[p] + off);
#pragma unroll
        for (int p = 0; p < NP; p++) {
            acc[p]      += v[p].x + v[p].y + v[p].z + v[p].w;
            acc[5 + p]  += v[p].x * v[p].x + v[p].y * v[p].y + v[p].z * v[p].z + v[p].w * v[p].w;
            acc[10 + p] += fabsf(v[p].x) + fabsf(v[p].y) + fabsf(v[p].z) + fabsf(v[p].w);
        }
        int k = 15;
#pragma unroll
        for (int p = 0; p < NP; p++)
#pragma unroll
            for (int q = p + 1; q < NP; q++) {
                acc[k] += v[p].x * v[q].x + v[p].y * v[q].y +
                          v[p].z * v[q].z + v[p].w * v[q].w;
                k++;
            }
    }

    // 8-lane butterfly (stays within each group: xor offsets 4,2,1)
#pragma unroll
    for (int i = 0; i < 25; i++) {
#pragma unroll
        for (int o = 4; o; o >>= 1)
            acc[i] += __shfl_xor_sync(0xffffffffu, acc[i], o);
    }

    if (gl == 0) {
        const float inv = 1.0f / 128.0f;
        float sq[NP];
#pragma unroll
        for (int p = 0; p < NP; p++) {
            float mean = acc[p] * inv;
            sq[p] = acc[5 + p];
            float l2 = sqrtf(sq[p]);
            float var = sq[p] * inv - mean * mean;
            float am  = acc[10 + p] * inv;
            __half* s = gate + h * (NP * 4) + p * 4;
            s[0] = __float2half_rn(mean); s[1] = __float2half_rn(var);
            s[2] = __float2half_rn(am);   s[3] = __float2half_rn(l2);
            gate[320 + h * NP + p] = __float2half_rn(l2);
        }
        int kk = 0;
#pragma unroll
        for (int p = 0; p < NP; p++)
#pragma unroll
            for (int q = p + 1; q < NP; q++) {
                float d2 = sq[p] + sq[q] - 2.0f * acc[15 + kk];
                gate[400 + h * 10 + kk] = __float2half_rn(sqrtf(fmaxf(d2, 0.0f)));
                kk++;
            }
    }
}

// ---------------------------------------------------------------------------
// GEMM1 fp16 mma + ldmatrix (R9 body), PDL consumer over fused prep.
// ---------------------------------------------------------------------------
__device__ __forceinline__ void g1_load(uint32_t stage_s,
                                        const __half* __restrict__ hid,
                                        const __half* __restrict__ st,
                                        const __half* __restrict__ Bm,
                                        int k0, int tid)
{
    const uint32_t a_s = stage_s;
    const uint32_t b_s = stage_s + G1_A_H * 2;
    const __half* asrc;
    int astride, ak;
    if (k0 < HIDDEN) { asrc = hid; astride = HIDDEN; ak = k0; }
    else             { asrc = st;  astride = STAT_W; ak = k0 - HIDDEN; }
#pragma unroll
    for (int j = 0; j < 4; j++) {
        const int idx = tid + j * 256;
        const int m  = idx >> 3;
        const int ks = (idx & 7) << 3;
        cp_async16(a_s + (uint32_t)(m * STRH + ks) * 2,
                   asrc + (size_t)m * astride + ak + ks);
    }
#pragma unroll
    for (int j = 0; j < 8; j++) {
        const int idx = tid + j * 256;
        const int m  = idx >> 3;
        const int ks = (idx & 7) << 3;
        cp_async16(b_s + (uint32_t)(m * STRH + ks) * 2,
                   Bm + (size_t)m * GATE_IN_PAD + k0 + ks);
    }
}

__global__ void __launch_bounds__(256, 1) gemm1_mma_kernel(const float* __restrict__ b1)
{
    GDC_WAIT();   // fused prep must be complete before any reads

    extern __shared__ __half smem[];
    const uint32_t s0 = smem_u32(smem);

    const int tid  = threadIdx.x;
    const int wid  = tid >> 5, lane = tid & 31;
    const int wm   = (wid & 1) * 64;
    const int wn   = (wid >> 1) * 64;
    const int g    = lane >> 2;
    const int t2   = (lane & 3) * 2;
    const int quad = lane >> 3;

    const uint32_t a_loff = (uint32_t)(((quad & 1) * 8 + (lane & 7)) * STRH + (quad >> 1) * 8);
    const uint32_t b_loff = (uint32_t)(((quad >> 1) * 8 + (lane & 7)) * STRH + (quad & 1) * 8);

    const __half* hid = g_hid_h + (size_t)blockIdx.y * 128 * HIDDEN;
    const __half* st  = g_stats + (size_t)blockIdx.y * 128 * STAT_W;
    const __half* Bm  = g_w1p   + (size_t)blockIdx.x * 256 * GATE_IN_PAD;

    float acc[4][8][4];
#pragma unroll
    for (int i = 0; i < 4; i++)
#pragma unroll
        for (int j = 0; j < 8; j++)
#pragma unroll
            for (int r = 0; r < 4; r++) acc[i][j][r] = 0.0f;

    g1_load(s0, hid, st, Bm, 0, tid);
    asm volatile("cp.async.commit_group;" ::: "memory");
    g1_load(s0 + G1_STAGE_B, hid, st, Bm, KCH, tid);
    asm volatile("cp.async.commit_group;" ::: "memory");

    int stage_rd = 0;
    for (int i = 0; i < NCHUNK; i++) {
        if (i + 2 < NCHUNK) {
            const int ws = (i + 2) % 3;
            g1_load(s0 + (uint32_t)ws * G1_STAGE_B, hid, st, Bm, (i + 2) * KCH, tid);
        }
        asm volatile("cp.async.commit_group;" ::: "memory");
        asm volatile("cp.async.wait_group 2;" ::: "memory");
        __syncthreads();

        const uint32_t as_u = s0 + (uint32_t)stage_rd * G1_STAGE_B;
        const uint32_t bs_u = as_u + G1_A_H * 2;

#pragma unroll
        for (int kk = 0; kk < KCH; kk += 16) {
            uint32_t a[4][4];
#pragma unroll
            for (int mi = 0; mi < 4; mi++)
                ldmatrix_x4(a[mi],
                            as_u + ((uint32_t)((wm + mi * 16) * STRH + kk) + a_loff) * 2);
            uint32_t b[4][4];
#pragma unroll
            for (int njp = 0; njp < 4; njp++)
                ldmatrix_x4(b[njp],
                            bs_u + ((uint32_t)((wn + njp * 16) * STRH + kk) + b_loff) * 2);
#pragma unroll
            for (int mi = 0; mi < 4; mi++)
#pragma unroll
                for (int njp = 0; njp < 4; njp++) {
                    mma_f16_16x8x16(acc[mi][njp * 2],     a[mi][0], a[mi][1], a[mi][2], a[mi][3],
                                    b[njp][0], b[njp][1]);
                    mma_f16_16x8x16(acc[mi][njp * 2 + 1], a[mi][0], a[mi][1], a[mi][2], a[mi][3],
                                    b[njp][2], b[njp][3]);
                }
        }
        __syncthreads();
        stage_rd = stage_rd + 1 == 3 ? 0 : stage_rd + 1;
    }

    const size_t row_base = (size_t)blockIdx.y * 128 + wm + g;
    const int    col_base = blockIdx.x * 256 + wn + t2;
#pragma unroll
    for (int nj = 0; nj < 8; nj++) {
        const int gc = col_base + nj * 8;
        const float2 bb = *reinterpret_cast<const float2*>(b1 + gc);
#pragma unroll
        for (int mi = 0; mi < 4; mi++) {
            const size_t r0 = row_base + mi * 16;
            __half2 o0 = __floats2half2_rn(gelu(acc[mi][nj][0] + bb.x),
                                           gelu(acc[mi][nj][1] + bb.y));
            __half2 o1 = __floats2half2_rn(gelu(acc[mi][nj][2] + bb.x),
                                           gelu(acc[mi][nj][3] + bb.y));
            *reinterpret_cast<__half2*>(g_h + r0 * GATE_HID + gc)       = o0;
            *reinterpret_cast<__half2*>(g_h + (r0 + 8) * GATE_HID + gc) = o1;
        }
    }
}

// ---------------------------------------------------------------------------
// GEMM2 fp16 mma + fused bias/softmax/clip/renorm (PDL producer+consumer).
// ---------------------------------------------------------------------------
__global__ void __launch_bounds__(256) gemm2_mma_kernel(
    const float* __restrict__ b2, const float* __restrict__ log_temp)
{
    GDC_TRIGGER();
    GDC_WAIT();

    extern __shared__ __half smem[];
    const uint32_t s0 = smem_u32(smem);

    const int tid  = threadIdx.x;
    const int wid  = tid >> 5, lane = tid & 31;
    const int mw   = wid >> 1;
    const int nw   = wid & 1;
    const int g    = lane >> 2;
    const int t2   = (lane & 3) * 2;

    const int tbase = blockIdx.x * 64;
    const __half* A = g_h + (size_t)tbase * GATE_HID;

    float acc[5][4];
#pragma unroll
    for (int j = 0; j < 5; j++)
#pragma unroll
        for (int r = 0; r < 4; r++) acc[j][r] = 0.0f;

    const uint32_t aoff[2] = {0u, (uint32_t)G2_A_H * 2};
    const uint32_t boff[2] = {(uint32_t)(2 * G2_A_H) * 2,
                              (uint32_t)(2 * G2_A_H + G2_B_H) * 2};

    {
#pragma unroll
        for (int j = 0; j < 2; j++) {
            const int idx = tid + j * 256;
            const int m = idx >> 3, ks = (idx & 7) << 3;
            cp_async16(s0 + aoff[0] + (uint32_t)(m * STRH + ks) * 2,
                       A + (size_t)m * GATE_HID + ks);
        }
#pragma unroll
        for (int j = 0; j < 3; j++) {
            const int idx = tid + j * 256;
            if (idx < 640) {
                const int m = idx >> 3, ks = (idx & 7) << 3;
                cp_async16(s0 + boff[0] + (uint32_t)(m * STRH + ks) * 2,
                           g_w2p + (size_t)m * GATE_HID + ks);
            }
        }
        asm volatile("cp.async.commit_group;" ::: "memory");
    }

    for (int i = 0; i < G2_NCH; i++) {
        const int s = i & 1;
        if (i + 1 < G2_NCH) {
            const int ns = (i + 1) & 1;
            const int k0 = (i + 1) * KCH;
#pragma unroll
            for (int j = 0; j < 2; j++) {
                const int idx = tid + j * 256;
                const int m = idx >> 3, ks = (idx & 7) << 3;
                cp_async16(s0 + aoff[ns] + (uint32_t)(m * STRH + ks) * 2,
                           A + (size_t)m * GATE_HID + k0 + ks);
            }
#pragma unroll
            for (int j = 0; j < 3; j++) {
                const int idx = tid + j * 256;
                if (idx < 640) {
                    const int m = idx >> 3, ks = (idx & 7) << 3;
                    cp_async16(s0 + boff[ns] + (uint32_t)(m * STRH + ks) * 2,
                               g_w2p + (size_t)m * GATE_HID + k0 + ks);
                }
            }
        }
        asm volatile("cp.async.commit_group;" ::: "memory");
        if (i + 1 < G2_NCH) asm volatile("cp.async.wait_group 1;" ::: "memory");
        else                asm volatile("cp.async.wait_group 0;" ::: "memory");
        __syncthreads();

        const __half* as = smem + (s ? G2_A_H : 0);
        const __half* bs = smem + 2 * G2_A_H + (s ? G2_B_H : 0);

#pragma unroll
        for (int kk = 0; kk < KCH; kk += 16) {
            const __half* r0 = as + (mw * 16 + g) * STRH + kk + t2;
            const __half* r1 = as + (mw * 16 + g + 8) * STRH + kk + t2;
            uint32_t a0 = *reinterpret_cast<const uint32_t*>(r0);
            uint32_t a1 = *reinterpret_cast<const uint32_t*>(r1);
            uint32_t a2 = *reinterpret_cast<const uint32_t*>(r0 + 8);
            uint32_t a3 = *reinterpret_cast<const uint32_t*>(r1 + 8);
#pragma unroll
            for (int nj = 0; nj < 5; nj++) {
                const __half* br = bs + (nw * 40 + nj * 8 + g) * STRH + kk + t2;
                mma_f16_16x8x16(acc[nj], a0, a1, a2, a3,
                                *reinterpret_cast<const uint32_t*>(br),
                                *reinterpret_cast<const uint32_t*>(br + 8));
            }
        }
        __syncthreads();
    }

    float* lg = reinterpret_cast<float*>(smem);
    {
        const int r0 = mw * 16 + g;
        const int c0 = nw * 40 + t2;
#pragma unroll
        for (int nj = 0; nj < 5; nj++) {
            const int c = c0 + nj * 8;
            lg[r0 * OUT_DIM + c]            = acc[nj][0];
            lg[r0 * OUT_DIM + c + 1]        = acc[nj][1];
            lg[(r0 + 8) * OUT_DIM + c]      = acc[nj][2];
            lg[(r0 + 8) * OUT_DIM + c + 1]  = acc[nj][3];
        }
    }
    __syncthreads();

#pragma unroll
    for (int it = 0; it < 4; it++) {
        const int idx = tid + it * 256;
        const int tt = idx >> 4, h = idx & 15;
        const float invt = expf(-log_temp[h]);
        float l[NP], mx = -1e30f;
#pragma unroll
        for (int p = 0; p < NP; p++) {
            l[p] = (lg[tt * OUT_DIM + h * NP + p] + __ldg(b2 + h * NP + p)) * invt;
            mx = fmaxf(mx, l[p]);
        }
        float e[NP], se = 0.f;
#pragma unroll
        for (int p = 0; p < NP; p++) { e[p] = expf(l[p] - mx); se += e[p]; }
        const float ise = 1.0f / se;
        float pr[NP], s2s = 0.f;
#pragma unroll
        for (int p = 0; p < NP; p++) { pr[p] = fmaxf(e[p] * ise, 0.02f); s2s += pr[p]; }
        const float is2 = 1.0f / s2s;
        float* dst = g_probs + (size_t)(tbase + tt) * OUT_DIM + h * NP;
#pragma unroll
        for (int p = 0; p < NP; p++) dst[p] = pr[p] * is2;
    }
}

// ---------------------------------------------------------------------------
// Output: PDL consumer — prefetch path data BEFORE waiting on gemm2's probs.
// ---------------------------------------------------------------------------
__global__ void __launch_bounds__(256) output_kernel(
    const float* __restrict__ p0, const float* __restrict__ p1,
    const float* __restrict__ p2, const float* __restrict__ p3,
    const float* __restrict__ p4, float* __restrict__ out, int n4)
{
    const int v = blockIdx.x * blockDim.x + threadIdx.x;
    if (v >= n4) { GDC_WAIT(); return; }
    const int t = v >> 9;
    const int h = (v >> 5) & 15;
    const float4 a0 = reinterpret_cast<const float4*>(p0)[v];
    const float4 a1 = reinterpret_cast<const float4*>(p1)[v];
    const float4 a2 = reinterpret_cast<const float4*>(p2)[v];
    const float4 a3 = reinterpret_cast<const float4*>(p3)[v];
    const float4 a4 = reinterpret_cast<const float4*>(p4)[v];
    GDC_WAIT();
    const float* pb = g_probs + (size_t)t * OUT_DIM + h * NP;
    const float w0 = pb[0], w1 = pb[1], w2 = pb[2], w3 = pb[3], w4 = pb[4];
    float4 o;
    o.x = a0.x * w0 + a1.x * w1 + a2.x * w2 + a3.x * w3 + a4.x * w4;
    o.y = a0.y * w0 + a1.y * w1 + a2.y * w2 + a3.y * w3 + a4.y * w4;
    o.z = a0.z * w0 + a1.z * w1 + a2.z * w2 + a3.z * w3 + a4.z * w4;
    o.w = a0.w * w0 + a1.w * w1 + a2.w * w2 + a3.w * w3 + a4.w * w4;
    reinterpret_cast<float4*>(out)[v] = o;
}

// ---------------------------------------------------------------------------
extern "C" void kernel_launch(void* const* d_in, const int* in_sizes, int n_in,
                              void* d_out, int out_size)
{
    const float* hidden = (const float*)d_in[0];
    const float* p0 = (const float*)d_in[1];
    const float* p1 = (const float*)d_in[2];
    const float* p2 = (const float*)d_in[3];
    const float* p3 = (const float*)d_in[4];
    const float* p4 = (const float*)d_in[5];
    const float* W1 = (const float*)d_in[6];
    const float* b1 = (const float*)d_in[7];
    const float* W2 = (const float*)d_in[8];
    const float* b2 = (const float*)d_in[9];
    const float* lt = (const float*)d_in[10];

    const int NT = in_sizes[0] / HIDDEN;   // 8192

    static int smem_set = 0;
    if (!smem_set) {
        cudaFuncSetAttribute(gemm1_mma_kernel,
                             cudaFuncAttributeMaxDynamicSharedMemorySize, GEMM1_SMEM);
        cudaFuncSetAttribute(gemm2_mma_kernel,
                             cudaFuncAttributeMaxDynamicSharedMemorySize, GEMM2_SMEM);
        smem_set = 1;
    }

    const int nout = NT * NH * HD;

    // 1) fused prep: stats (8-lane reductions) + hidden convert + W packs + tail
    fused_prep_kernel<<<NB_TOTAL, 128>>>(hidden, p0, p1, p2, p3, p4,
                                         W1, W2, (float*)d_out, nout, out_size);

    cudaLaunchAttribute attr[1];
    attr[0].id = cudaLaunchAttributeProgrammaticStreamSerialization;
    attr[0].val.programmaticStreamSerializationAllowed = 1;

    // 2) gemm1 — PSS over prep (waits at kernel top)
    {
        cudaLaunchConfig_t cfg = {};
        cfg.gridDim = dim3(GATE_HID / 256, NT / 128);   // (4, 64)
        cfg.blockDim = dim3(256);
        cfg.dynamicSmemBytes = GEMM1_SMEM;
        cfg.stream = 0;
        cfg.attrs = attr;
        cfg.numAttrs = 1;
        cudaLaunchKernelEx(&cfg, gemm1_mma_kernel, b1);
    }

    // 3) gemm2 — PSS over gemm1, triggers early for output
    {
        cudaLaunchConfig_t cfg = {};
        cfg.gridDim = dim3(NT / 64);
        cfg.blockDim = dim3(256);
        cfg.dynamicSmemBytes = GEMM2_SMEM;
        cfg.stream = 0;
        cfg.attrs = attr;
        cfg.numAttrs = 1;
        cudaLaunchKernelEx(&cfg, gemm2_mma_kernel, b2, lt);
    }

    // 4) output — PSS over gemm2; prefetches paths before waiting on probs
    {
        const int n4 = NT * (NH * HD) / 4;
        cudaLaunchConfig_t cfg = {};
        cfg.gridDim = dim3((n4 + 255) / 256);
        cfg.blockDim = dim3(256);
        cfg.dynamicSmemBytes = 0;
        cfg.stream = 0;
        cfg.attrs = attr;
        cfg.numAttrs = 1;
        cudaLaunchKernelEx(&cfg, output_kernel, p0, p1, p2, p3, p4, (float*)d_out, n4);
    }
}